// round 2
// baseline (speedup 1.0000x reference)
#include <cuda_runtime.h>
#include <math.h>

#define NN 50000
#define EE 800000
#define D0 192
#define D1 208
#define BB 64
#define RT 32
#define RS 36
#define NPB 128
#define EPSV 1e-5f
#define NEGINF __int_as_float(0xff800000)

// ---------------- device scratch ----------------
__device__ __align__(16) float g_xa[NN*16];
__device__ __align__(16) float g_A[NN*4];
__device__ __align__(16) float g_deg[NN];
__device__ __align__(16) float g_xaa[NN*16];
__device__ __align__(16) float g_Aa[NN*4];
__device__ __align__(16) float g_dega[NN];
__device__ __align__(16) float g_pre1[(size_t)NN*D0];
__device__ __align__(16) float g_h2[(size_t)NN*D1];
__device__ float g_sum1[D0], g_sq1[D0], g_s1[D0], g_t1[D0];
__device__ float g_sum2[D1], g_sq2[D1], g_s2[D1], g_t2[D1];
__device__ float g_G[59*D1];
__device__ float g_S[BB*416], g_M[BB*416], g_cnt[BB];

// ---------------- helpers ----------------
__device__ __forceinline__ void red4(float* addr, float4 v){
    asm volatile("red.global.add.v4.f32 [%0], {%1,%2,%3,%4};"
                 :: "l"(addr), "f"(v.x), "f"(v.y), "f"(v.z), "f"(v.w) : "memory");
}
__device__ __forceinline__ void atomicMaxF(float* a, float v){
    if (v >= 0.0f) atomicMax((int*)a, __float_as_int(v));
    else           atomicMin((unsigned int*)a, __float_as_uint(v));
}

// ---------------- kernels ----------------
__global__ void k_zero(){
    int tid = blockIdx.x*blockDim.x + threadIdx.x;
    int st  = gridDim.x*blockDim.x;
    for (int i=tid;i<NN*16;i+=st){ g_xa[i]=0.f; g_xaa[i]=0.f; }
    for (int i=tid;i<NN*4; i+=st){ g_A[i]=0.f;  g_Aa[i]=0.f;  }
    for (int i=tid;i<NN;   i+=st){ g_deg[i]=0.f; g_dega[i]=0.f; }
    for (int i=tid;i<BB*416;i+=st){ g_S[i]=0.f; g_M[i]=NEGINF; }
    if (tid < D0){ g_sum1[tid]=0.f; g_sq1[tid]=0.f; }
    if (tid < D1){ g_sum2[tid]=0.f; g_sq2[tid]=0.f; }
    if (tid < BB) g_cnt[tid]=0.f;
}

__global__ void k_edge1(const int* __restrict__ src, const int* __restrict__ dst,
                        const float* __restrict__ ea, const float* __restrict__ x){
    int e = blockIdx.x*blockDim.x + threadIdx.x;
    if (e >= EE) return;
    int s = src[e], d = dst[e];
    const float4* xr = (const float4*)(x + (size_t)s*16);
    float4 v0=xr[0], v1=xr[1], v2=xr[2], v3=xr[3];
    float* xd = g_xa + (size_t)d*16;
    red4(xd, v0); red4(xd+4, v1); red4(xd+8, v2); red4(xd+12, v3);
    float4 a = ((const float4*)ea)[e];
    red4(g_A + (size_t)d*4, a);
    atomicAdd(g_deg + d, 1.0f);
}

__global__ void k_edge2(const int* __restrict__ src, const int* __restrict__ dst){
    int e = blockIdx.x*blockDim.x + threadIdx.x;
    if (e >= EE) return;
    int s = src[e], d = dst[e];
    const float4* xr = (const float4*)(g_xa + (size_t)s*16);
    float4 v0=xr[0], v1=xr[1], v2=xr[2], v3=xr[3];
    float* xd = g_xaa + (size_t)d*16;
    red4(xd, v0); red4(xd+4, v1); red4(xd+8, v2); red4(xd+12, v3);
    float4 a = *((const float4*)(g_A + (size_t)s*4));
    red4(g_Aa + (size_t)d*4, a);
    atomicAdd(g_dega + d, g_deg[s]);
}

// h1_pre = xa@Wm1 + A@We1 + x@Ws1 + deg*(bm1+be1b) + bs1 ; accumulate BN1 stats
__global__ __launch_bounds__(192) void k_pre1(
        const float* __restrict__ Wm1, const float* __restrict__ bm1,
        const float* __restrict__ We1, const float* __restrict__ be1b,
        const float* __restrict__ Ws1, const float* __restrict__ bs1,
        const float* __restrict__ x){
    __shared__ float fsm[37*RS];
    int c = threadIdx.x;
    float w[37];
    #pragma unroll
    for (int k=0;k<16;k++) w[k]    = Wm1[k*D0+c];
    #pragma unroll
    for (int k=0;k<4;k++)  w[16+k] = We1[k*D0+c];
    #pragma unroll
    for (int k=0;k<16;k++) w[20+k] = Ws1[k*D0+c];
    w[36] = bm1[c] + be1b[c];
    float initv = bs1[c];
    float lsum=0.f, lsq=0.f;
    int brow = blockIdx.x*256;
    for (int tile=0; tile<8; ++tile){
        int row0 = brow + tile*RT;
        __syncthreads();
        for (int idx=threadIdx.x; idx<RT*16; idx+=192){
            int r=idx>>4, k=idx&15; int row=row0+r; bool ok=row<NN;
            fsm[k*RS+r]      = ok ? g_xa[(size_t)row*16+k] : 0.f;
            fsm[(20+k)*RS+r] = ok ? x[(size_t)row*16+k]    : 0.f;
        }
        for (int idx=threadIdx.x; idx<RT*4; idx+=192){
            int r=idx>>2, k=idx&3; int row=row0+r; bool ok=row<NN;
            fsm[(16+k)*RS+r] = ok ? g_A[(size_t)row*4+k] : 0.f;
        }
        for (int idx=threadIdx.x; idx<RT; idx+=192){
            int row=row0+idx;
            fsm[36*RS+idx] = (row<NN) ? g_deg[row] : 0.f;
        }
        __syncthreads();
        for (int g4=0; g4<RT/4; ++g4){
            float4 acc = make_float4(initv,initv,initv,initv);
            const float* fp = fsm + g4*4;
            #pragma unroll
            for (int k=0;k<37;k++){
                float4 fv = *(const float4*)(fp + k*RS);
                acc.x = fmaf(w[k], fv.x, acc.x);
                acc.y = fmaf(w[k], fv.y, acc.y);
                acc.z = fmaf(w[k], fv.z, acc.z);
                acc.w = fmaf(w[k], fv.w, acc.w);
            }
            float vals[4] = {acc.x, acc.y, acc.z, acc.w};
            int rb = row0 + g4*4;
            #pragma unroll
            for (int q=0;q<4;q++){
                int row = rb+q;
                if (row<NN){
                    g_pre1[(size_t)row*D0+c] = vals[q];
                    lsum += vals[q]; lsq = fmaf(vals[q], vals[q], lsq);
                }
            }
        }
    }
    atomicAdd(&g_sum1[c], lsum);
    atomicAdd(&g_sq1[c],  lsq);
}

__global__ void k_stats1(const float* __restrict__ g1, const float* __restrict__ be1){
    int c = threadIdx.x;
    float m = g_sum1[c]*(1.0f/NN);
    float v = g_sq1[c]*(1.0f/NN) - m*m;
    float s = g1[c]*rsqrtf(v+EPSV);
    g_s1[c] = s; g_t1[c] = be1[c] - m*s;
}

// G[59,208]: h2_pre = F @ G,  F=[xaa(16),Aa(4),xa(16),A(4),x(16),dega,deg,1]
__global__ void k_composeG(
        const float* __restrict__ Wm1, const float* __restrict__ We1,
        const float* __restrict__ Ws1, const float* __restrict__ bm1,
        const float* __restrict__ be1b, const float* __restrict__ bs1,
        const float* __restrict__ Wm2, const float* __restrict__ We2,
        const float* __restrict__ bm2, const float* __restrict__ be2b){
    int c = threadIdx.x;          // 0..207
    int f = blockIdx.x;           // 0..58
    float acc = 0.f;
    if (f < 16){
        const float* wr = Wm1 + f*D0;
        for (int j=0;j<D0;j++) acc = fmaf(wr[j]*g_s1[j], Wm2[j*D1+c], acc);
    } else if (f < 20){
        const float* wr = We1 + (f-16)*D0;
        for (int j=0;j<D0;j++) acc = fmaf(wr[j]*g_s1[j], Wm2[j*D1+c], acc);
    } else if (f < 36){
        int k = f-20;
        const float* wr = Ws1 + k*D0;
        for (int j=0;j<D0;j++) acc = fmaf(wr[j]*g_s1[j], Wm2[j*D1+c], acc);
        acc += Wm2[(D0+k)*D1+c];
        if (c < D0) acc += Wm1[k*D0+c]*g_s1[c];
    } else if (f < 40){
        int k = f-36;
        acc = We2[k*D1+c] + ((c<D0) ? We1[k*D0+c]*g_s1[c] : 0.f);
    } else if (f < 56){
        int k = f-40;
        acc = (c<D0) ? Ws1[k*D0+c]*g_s1[c] : ((c-D0==k) ? 1.f : 0.f);
    } else if (f == 56){
        for (int j=0;j<D0;j++) acc = fmaf((bm1[j]+be1b[j])*g_s1[j], Wm2[j*D1+c], acc);
    } else if (f == 57){
        for (int j=0;j<D0;j++) acc = fmaf(bs1[j]*g_s1[j]+g_t1[j], Wm2[j*D1+c], acc);
        acc += bm2[c]+be2b[c];
        if (c < D0) acc += (bm1[c]+be1b[c])*g_s1[c];
    } else {
        acc = (c<D0) ? bs1[c]*g_s1[c]+g_t1[c] : 0.f;
    }
    g_G[f*D1+c] = acc;
}

// h2_pre = F @ G ; accumulate BN2 stats
__global__ __launch_bounds__(208) void k_h2(const float* __restrict__ x){
    __shared__ float fsm[59*RS];
    int c = threadIdx.x;
    float w[59];
    #pragma unroll
    for (int f=0; f<59; f++) w[f] = g_G[f*D1+c];
    float lsum=0.f, lsq=0.f;
    int brow = blockIdx.x*256;
    for (int tile=0; tile<8; ++tile){
        int row0 = brow + tile*RT;
        __syncthreads();
        for (int idx=threadIdx.x; idx<RT*16; idx+=208){
            int r=idx>>4, k=idx&15; int row=row0+r; bool ok=row<NN;
            fsm[k*RS+r]      = ok ? g_xaa[(size_t)row*16+k] : 0.f;
            fsm[(20+k)*RS+r] = ok ? g_xa [(size_t)row*16+k] : 0.f;
            fsm[(40+k)*RS+r] = ok ? x    [(size_t)row*16+k] : 0.f;
        }
        for (int idx=threadIdx.x; idx<RT*4; idx+=208){
            int r=idx>>2, k=idx&3; int row=row0+r; bool ok=row<NN;
            fsm[(16+k)*RS+r] = ok ? g_Aa[(size_t)row*4+k] : 0.f;
            fsm[(36+k)*RS+r] = ok ? g_A [(size_t)row*4+k] : 0.f;
        }
        for (int idx=threadIdx.x; idx<RT; idx+=208){
            int row=row0+idx; bool ok=row<NN;
            fsm[56*RS+idx] = ok ? g_dega[row] : 0.f;
            fsm[57*RS+idx] = ok ? g_deg[row]  : 0.f;
            fsm[58*RS+idx] = ok ? 1.f : 0.f;
        }
        __syncthreads();
        for (int g4=0; g4<RT/4; ++g4){
            float4 acc = make_float4(0.f,0.f,0.f,0.f);
            const float* fp = fsm + g4*4;
            #pragma unroll
            for (int k=0;k<59;k++){
                float4 fv = *(const float4*)(fp + k*RS);
                acc.x = fmaf(w[k], fv.x, acc.x);
                acc.y = fmaf(w[k], fv.y, acc.y);
                acc.z = fmaf(w[k], fv.z, acc.z);
                acc.w = fmaf(w[k], fv.w, acc.w);
            }
            float vals[4] = {acc.x, acc.y, acc.z, acc.w};
            int rb = row0 + g4*4;
            #pragma unroll
            for (int q=0;q<4;q++){
                int row = rb+q;
                if (row<NN){
                    g_h2[(size_t)row*D1+c] = vals[q];
                    lsum += vals[q]; lsq = fmaf(vals[q], vals[q], lsq);
                }
            }
        }
    }
    atomicAdd(&g_sum2[c], lsum);
    atomicAdd(&g_sq2[c],  lsq);
}

__global__ void k_stats2(const float* __restrict__ g2, const float* __restrict__ be2){
    int c = threadIdx.x;
    float m = g_sum2[c]*(1.0f/NN);
    float v = g_sq2[c]*(1.0f/NN) - m*m;
    float s = g2[c]*rsqrtf(v+EPSV);
    g_s2[c] = s; g_t2[c] = be2[c] - m*s;
}

// pooling: x2=[h2, h1, x]; per-channel thread scans sorted batch, flush on change
__global__ __launch_bounds__(416) void k_pool(const int* __restrict__ batch,
                                              const float* __restrict__ x){
    int c = threadIdx.x;
    int n0 = blockIdx.x*NPB;
    int n1 = min(n0+NPB, NN);
    if (n0 >= NN) return;
    float sc=1.f, tc=0.f;
    if (c < D1){ sc = g_s2[c]; tc = g_t2[c]; }
    else if (c < 400){ sc = g_s1[c-D1]; tc = g_t1[c-D1]; }
    float sum=0.f, mx=NEGINF;
    int cur = batch[n0];
    int runstart = n0;
    for (int n=n0; n<n1; ++n){
        int b = batch[n];
        if (b != cur){
            atomicAdd(&g_S[cur*416+c], sum);
            atomicMaxF(&g_M[cur*416+c], mx);
            if (c==0) atomicAdd(&g_cnt[cur], (float)(n-runstart));
            sum=0.f; mx=NEGINF; cur=b; runstart=n;
        }
        float v;
        if (c < D1)       v = g_h2  [(size_t)n*D1 + c]      *sc + tc;
        else if (c < 400) v = g_pre1[(size_t)n*D0 + (c-D1)] *sc + tc;
        else              v = x[(size_t)n*16 + (c-400)];
        sum += v; mx = fmaxf(mx, v);
    }
    atomicAdd(&g_S[cur*416+c], sum);
    atomicMaxF(&g_M[cur*416+c], mx);
    if (c==0) atomicAdd(&g_cnt[cur], (float)(n1-runstart));
}

// head: pooled[1248] @ W_l1 -> PReLU -> @ W_l2 -> log_softmax
__global__ __launch_bounds__(624) void k_head(
        const float* __restrict__ Wl1, const float* __restrict__ bl1,
        const float* __restrict__ alpha, const float* __restrict__ Wl2,
        const float* __restrict__ bl2, float* __restrict__ out){
    __shared__ float pl[1248];
    __shared__ float l0s, l1s;
    int b = blockIdx.x, j = threadIdx.x;
    float cnt = fmaxf(g_cnt[b], 1.f);
    for (int i=j; i<416; i+=624){
        float s = g_S[b*416+i];
        pl[i]      = s;
        pl[416+i]  = g_M[b*416+i];
        pl[832+i]  = s/cnt;
    }
    if (j==0){ l0s=0.f; l1s=0.f; }
    __syncthreads();
    float acc = bl1[j];
    for (int k=0;k<1248;k++) acc = fmaf(pl[k], Wl1[k*624+j], acc);
    float h = (acc >= 0.f) ? acc : alpha[0]*acc;
    atomicAdd(&l0s, h*Wl2[j*2+0]);
    atomicAdd(&l1s, h*Wl2[j*2+1]);
    __syncthreads();
    if (j==0){
        float a0 = l0s+bl2[0], a1 = l1s+bl2[1];
        float m = fmaxf(a0,a1);
        float lse = m + logf(expf(a0-m)+expf(a1-m));
        out[b*2+0] = a0-lse;
        out[b*2+1] = a1-lse;
    }
}

extern "C" void kernel_launch(void* const* d_in, const int* in_sizes, int n_in,
                              void* d_out, int out_size) {
    const float* x    = (const float*)d_in[0];
    const int*   ei   = (const int*)  d_in[1];
    const float* ea   = (const float*)d_in[2];
    const int*   batch= (const int*)  d_in[3];
    const float* Wm1  = (const float*)d_in[4];
    const float* bm1  = (const float*)d_in[5];
    const float* We1  = (const float*)d_in[6];
    const float* be1b = (const float*)d_in[7];
    const float* Ws1  = (const float*)d_in[8];
    const float* bs1  = (const float*)d_in[9];
    const float* g1   = (const float*)d_in[10];
    const float* be1  = (const float*)d_in[11];
    const float* Wm2  = (const float*)d_in[12];
    const float* bm2  = (const float*)d_in[13];
    const float* We2  = (const float*)d_in[14];
    const float* be2b = (const float*)d_in[15];
    const float* g2   = (const float*)d_in[16];
    const float* be2  = (const float*)d_in[17];
    const float* Wl1  = (const float*)d_in[18];
    const float* bl1  = (const float*)d_in[19];
    const float* alpha= (const float*)d_in[20];
    const float* Wl2  = (const float*)d_in[21];
    const float* bl2  = (const float*)d_in[22];
    const int* src = ei;
    const int* dst = ei + EE;
    float* out = (float*)d_out;

    k_zero<<<1024, 256>>>();
    k_edge1<<<(EE+255)/256, 256>>>(src, dst, ea, x);
    k_edge2<<<(EE+255)/256, 256>>>(src, dst);
    k_pre1<<<(NN+255)/256, 192>>>(Wm1, bm1, We1, be1b, Ws1, bs1, x);
    k_stats1<<<1, D0>>>(g1, be1);
    k_composeG<<<59, D1>>>(Wm1, We1, Ws1, bm1, be1b, bs1, Wm2, We2, bm2, be2b);
    k_h2<<<(NN+255)/256, D1>>>(x);
    k_stats2<<<1, D1>>>(g2, be2);
    k_pool<<<(NN+NPB-1)/NPB, 416>>>(batch, x);
    k_head<<<BB, 624>>>(Wl1, bl1, alpha, Wl2, bl2, out);
}

// round 3
// speedup vs baseline: 1.3992x; 1.3992x over previous
#include <cuda_runtime.h>
#include <math.h>

#define NN 50000
#define EE 800000
#define D0 192
#define D1 208
#define BB 64
#define RT 32
#define RS 36
#define EPSV 1e-5f
#define NEGINF __int_as_float(0xff800000)
#define POSINF __int_as_float(0x7f800000)

// ---------------- device scratch ----------------
__device__ __align__(16) float g_xa[NN*16];
__device__ __align__(16) float g_A[NN*4];
__device__ __align__(16) float g_deg[NN];
__device__ __align__(16) float g_xaa[NN*16];
__device__ __align__(16) float g_Aa[NN*4];
__device__ __align__(16) float g_dega[NN];
__device__ float g_sum1[D0], g_sq1[D0], g_s1[D0], g_t1[D0];
__device__ float g_sum2[D1], g_sq2[D1], g_s2[D1], g_t2[D1];
__device__ float g_G[59*D1];
// raw (pre-affine) pooled aggregates
__device__ float g_S1[BB*D0], g_Mx1[BB*D0], g_Mn1[BB*D0];
__device__ float g_S2[BB*D1], g_Mx2[BB*D1], g_Mn2[BB*D1];
__device__ float g_Sx[BB*16], g_Mxx[BB*16];
__device__ float g_cnt[BB];
__device__ float g_pooled[BB*1248];
__device__ float g_hidden[BB*624];

// ---------------- helpers ----------------
__device__ __forceinline__ void red4(float* addr, float4 v){
    asm volatile("red.global.add.v4.f32 [%0], {%1,%2,%3,%4};"
                 :: "l"(addr), "f"(v.x), "f"(v.y), "f"(v.z), "f"(v.w) : "memory");
}
__device__ __forceinline__ void atomicMaxF(float* a, float v){
    if (v >= 0.0f) atomicMax((int*)a, __float_as_int(v));
    else           atomicMin((unsigned int*)a, __float_as_uint(v));
}
__device__ __forceinline__ void atomicMinF(float* a, float v){
    if (v >= 0.0f) atomicMin((int*)a, __float_as_int(v));
    else           atomicMax((unsigned int*)a, __float_as_uint(v));
}

// ---------------- kernels ----------------
__global__ void k_zero(){
    int tid = blockIdx.x*blockDim.x + threadIdx.x;
    int st  = gridDim.x*blockDim.x;
    for (int i=tid;i<NN*16;i+=st){ g_xa[i]=0.f; g_xaa[i]=0.f; }
    for (int i=tid;i<NN*4; i+=st){ g_A[i]=0.f;  g_Aa[i]=0.f;  }
    for (int i=tid;i<NN;   i+=st){ g_deg[i]=0.f; g_dega[i]=0.f; }
    for (int i=tid;i<BB*D0;i+=st){ g_S1[i]=0.f; g_Mx1[i]=NEGINF; g_Mn1[i]=POSINF; }
    for (int i=tid;i<BB*D1;i+=st){ g_S2[i]=0.f; g_Mx2[i]=NEGINF; g_Mn2[i]=POSINF; }
    for (int i=tid;i<BB*16;i+=st){ g_Sx[i]=0.f; g_Mxx[i]=NEGINF; }
    if (tid < D0){ g_sum1[tid]=0.f; g_sq1[tid]=0.f; }
    if (tid < D1){ g_sum2[tid]=0.f; g_sq2[tid]=0.f; }
    if (tid < BB) g_cnt[tid]=0.f;
}

__global__ void k_edge1(const int* __restrict__ src, const int* __restrict__ dst,
                        const float* __restrict__ ea, const float* __restrict__ x){
    int e = blockIdx.x*blockDim.x + threadIdx.x;
    if (e >= EE) return;
    int s = src[e], d = dst[e];
    const float4* xr = (const float4*)(x + (size_t)s*16);
    float4 v0=xr[0], v1=xr[1], v2=xr[2], v3=xr[3];
    float* xd = g_xa + (size_t)d*16;
    red4(xd, v0); red4(xd+4, v1); red4(xd+8, v2); red4(xd+12, v3);
    float4 a = ((const float4*)ea)[e];
    red4(g_A + (size_t)d*4, a);
    atomicAdd(g_deg + d, 1.0f);
}

__global__ void k_edge2(const int* __restrict__ src, const int* __restrict__ dst){
    int e = blockIdx.x*blockDim.x + threadIdx.x;
    if (e >= EE) return;
    int s = src[e], d = dst[e];
    const float4* xr = (const float4*)(g_xa + (size_t)s*16);
    float4 v0=xr[0], v1=xr[1], v2=xr[2], v3=xr[3];
    float* xd = g_xaa + (size_t)d*16;
    red4(xd, v0); red4(xd+4, v1); red4(xd+8, v2); red4(xd+12, v3);
    float4 a = *((const float4*)(g_A + (size_t)s*4));
    red4(g_Aa + (size_t)d*4, a);
    atomicAdd(g_dega + d, g_deg[s]);
}

// h1_pre GEMM fused with BN1 stats + run-flush pooling of raw h1_pre and x
__global__ __launch_bounds__(192) void k_pre1(
        const float* __restrict__ Wm1, const float* __restrict__ bm1,
        const float* __restrict__ We1, const float* __restrict__ be1b,
        const float* __restrict__ Ws1, const float* __restrict__ bs1,
        const float* __restrict__ x, const int* __restrict__ batch){
    __shared__ float fsm[37*RS];
    __shared__ int sbat[RT];
    int c = threadIdx.x;
    float w[37];
    #pragma unroll
    for (int k=0;k<16;k++) w[k]    = Wm1[k*D0+c];
    #pragma unroll
    for (int k=0;k<4;k++)  w[16+k] = We1[k*D0+c];
    #pragma unroll
    for (int k=0;k<16;k++) w[20+k] = Ws1[k*D0+c];
    w[36] = bm1[c] + be1b[c];
    float initv = bs1[c];
    float lsum=0.f, lsq=0.f;
    int cur=-1; float rsum=0.f, rmx=NEGINF, rmn=POSINF;
    float xs=0.f, xmx=NEGINF, rcnt=0.f;
    int brow = blockIdx.x*64;
    for (int tile=0; tile<2; ++tile){
        int row0 = brow + tile*RT;
        __syncthreads();
        for (int idx=threadIdx.x; idx<RT*16; idx+=192){
            int r=idx>>4, k=idx&15; int row=row0+r; bool ok=row<NN;
            fsm[k*RS+r]      = ok ? g_xa[(size_t)row*16+k] : 0.f;
            fsm[(20+k)*RS+r] = ok ? x[(size_t)row*16+k]    : 0.f;
        }
        for (int idx=threadIdx.x; idx<RT*4; idx+=192){
            int r=idx>>2, k=idx&3; int row=row0+r; bool ok=row<NN;
            fsm[(16+k)*RS+r] = ok ? g_A[(size_t)row*4+k] : 0.f;
        }
        for (int idx=threadIdx.x; idx<RT; idx+=192){
            int row=row0+idx;
            fsm[36*RS+idx] = (row<NN) ? g_deg[row] : 0.f;
            sbat[idx] = (row<NN) ? batch[row] : -1;
        }
        __syncthreads();
        for (int g4=0; g4<RT/4; ++g4){
            float4 acc = make_float4(initv,initv,initv,initv);
            const float* fp = fsm + g4*4;
            #pragma unroll
            for (int k=0;k<37;k++){
                float4 fv = *(const float4*)(fp + k*RS);
                acc.x = fmaf(w[k], fv.x, acc.x);
                acc.y = fmaf(w[k], fv.y, acc.y);
                acc.z = fmaf(w[k], fv.z, acc.z);
                acc.w = fmaf(w[k], fv.w, acc.w);
            }
            float vals[4] = {acc.x, acc.y, acc.z, acc.w};
            #pragma unroll
            for (int q=0;q<4;q++){
                int r = g4*4+q; int row = row0+r;
                if (row<NN){
                    float v = vals[q];
                    lsum += v; lsq = fmaf(v,v,lsq);
                    int b = sbat[r];
                    if (b != cur){
                        if (cur >= 0){
                            atomicAdd(&g_S1[cur*D0+c], rsum);
                            atomicMaxF(&g_Mx1[cur*D0+c], rmx);
                            atomicMinF(&g_Mn1[cur*D0+c], rmn);
                            if (c<16){ atomicAdd(&g_Sx[cur*16+c], xs); atomicMaxF(&g_Mxx[cur*16+c], xmx); }
                            if (c==0) atomicAdd(&g_cnt[cur], rcnt);
                        }
                        rsum=0.f; rmx=NEGINF; rmn=POSINF; xs=0.f; xmx=NEGINF; rcnt=0.f; cur=b;
                    }
                    rsum += v; rmx = fmaxf(rmx,v); rmn = fminf(rmn,v);
                    if (c<16){ float xv = fsm[(20+c)*RS+r]; xs += xv; xmx = fmaxf(xmx,xv); }
                    if (c==0) rcnt += 1.f;
                }
            }
        }
    }
    if (cur >= 0){
        atomicAdd(&g_S1[cur*D0+c], rsum);
        atomicMaxF(&g_Mx1[cur*D0+c], rmx);
        atomicMinF(&g_Mn1[cur*D0+c], rmn);
        if (c<16){ atomicAdd(&g_Sx[cur*16+c], xs); atomicMaxF(&g_Mxx[cur*16+c], xmx); }
        if (c==0) atomicAdd(&g_cnt[cur], rcnt);
    }
    atomicAdd(&g_sum1[c], lsum);
    atomicAdd(&g_sq1[c],  lsq);
}

__global__ void k_stats1(const float* __restrict__ g1, const float* __restrict__ be1){
    int c = threadIdx.x;
    float m = g_sum1[c]*(1.0f/NN);
    float v = g_sq1[c]*(1.0f/NN) - m*m;
    float s = g1[c]*rsqrtf(v+EPSV);
    g_s1[c] = s; g_t1[c] = be1[c] - m*s;
}

// G[59,208]: h2_pre = F @ G,  F=[xaa(16),Aa(4),xa(16),A(4),x(16),dega,deg,1]
__global__ void k_composeG(
        const float* __restrict__ Wm1, const float* __restrict__ We1,
        const float* __restrict__ Ws1, const float* __restrict__ bm1,
        const float* __restrict__ be1b, const float* __restrict__ bs1,
        const float* __restrict__ Wm2, const float* __restrict__ We2,
        const float* __restrict__ bm2, const float* __restrict__ be2b){
    int c = threadIdx.x;
    int f = blockIdx.x;
    float acc = 0.f;
    if (f < 16){
        const float* wr = Wm1 + f*D0;
        for (int j=0;j<D0;j++) acc = fmaf(wr[j]*g_s1[j], Wm2[j*D1+c], acc);
    } else if (f < 20){
        const float* wr = We1 + (f-16)*D0;
        for (int j=0;j<D0;j++) acc = fmaf(wr[j]*g_s1[j], Wm2[j*D1+c], acc);
    } else if (f < 36){
        int k = f-20;
        const float* wr = Ws1 + k*D0;
        for (int j=0;j<D0;j++) acc = fmaf(wr[j]*g_s1[j], Wm2[j*D1+c], acc);
        acc += Wm2[(D0+k)*D1+c];
        if (c < D0) acc += Wm1[k*D0+c]*g_s1[c];
    } else if (f < 40){
        int k = f-36;
        acc = We2[k*D1+c] + ((c<D0) ? We1[k*D0+c]*g_s1[c] : 0.f);
    } else if (f < 56){
        int k = f-40;
        acc = (c<D0) ? Ws1[k*D0+c]*g_s1[c] : ((c-D0==k) ? 1.f : 0.f);
    } else if (f == 56){
        for (int j=0;j<D0;j++) acc = fmaf((bm1[j]+be1b[j])*g_s1[j], Wm2[j*D1+c], acc);
    } else if (f == 57){
        for (int j=0;j<D0;j++) acc = fmaf(bs1[j]*g_s1[j]+g_t1[j], Wm2[j*D1+c], acc);
        acc += bm2[c]+be2b[c];
        if (c < D0) acc += (bm1[c]+be1b[c])*g_s1[c];
    } else {
        acc = (c<D0) ? bs1[c]*g_s1[c]+g_t1[c] : 0.f;
    }
    g_G[f*D1+c] = acc;
}

// h2_pre = F @ G fused with BN2 stats + run-flush pooling of raw h2_pre
__global__ __launch_bounds__(208) void k_h2(const float* __restrict__ x,
                                            const int* __restrict__ batch){
    __shared__ float fsm[59*RS];
    __shared__ int sbat[RT];
    int c = threadIdx.x;
    float w[59];
    #pragma unroll
    for (int f=0; f<59; f++) w[f] = g_G[f*D1+c];
    float lsum=0.f, lsq=0.f;
    int cur=-1; float rsum=0.f, rmx=NEGINF, rmn=POSINF;
    int brow = blockIdx.x*64;
    for (int tile=0; tile<2; ++tile){
        int row0 = brow + tile*RT;
        __syncthreads();
        for (int idx=threadIdx.x; idx<RT*16; idx+=208){
            int r=idx>>4, k=idx&15; int row=row0+r; bool ok=row<NN;
            fsm[k*RS+r]      = ok ? g_xaa[(size_t)row*16+k] : 0.f;
            fsm[(20+k)*RS+r] = ok ? g_xa [(size_t)row*16+k] : 0.f;
            fsm[(40+k)*RS+r] = ok ? x    [(size_t)row*16+k] : 0.f;
        }
        for (int idx=threadIdx.x; idx<RT*4; idx+=208){
            int r=idx>>2, k=idx&3; int row=row0+r; bool ok=row<NN;
            fsm[(16+k)*RS+r] = ok ? g_Aa[(size_t)row*4+k] : 0.f;
            fsm[(36+k)*RS+r] = ok ? g_A [(size_t)row*4+k] : 0.f;
        }
        for (int idx=threadIdx.x; idx<RT; idx+=208){
            int row=row0+idx; bool ok=row<NN;
            fsm[56*RS+idx] = ok ? g_dega[row] : 0.f;
            fsm[57*RS+idx] = ok ? g_deg[row]  : 0.f;
            fsm[58*RS+idx] = ok ? 1.f : 0.f;
            sbat[idx] = ok ? batch[row] : -1;
        }
        __syncthreads();
        for (int g4=0; g4<RT/4; ++g4){
            float4 acc = make_float4(0.f,0.f,0.f,0.f);
            const float* fp = fsm + g4*4;
            #pragma unroll
            for (int k=0;k<59;k++){
                float4 fv = *(const float4*)(fp + k*RS);
                acc.x = fmaf(w[k], fv.x, acc.x);
                acc.y = fmaf(w[k], fv.y, acc.y);
                acc.z = fmaf(w[k], fv.z, acc.z);
                acc.w = fmaf(w[k], fv.w, acc.w);
            }
            float vals[4] = {acc.x, acc.y, acc.z, acc.w};
            #pragma unroll
            for (int q=0;q<4;q++){
                int r = g4*4+q; int row = row0+r;
                if (row<NN){
                    float v = vals[q];
                    lsum += v; lsq = fmaf(v,v,lsq);
                    int b = sbat[r];
                    if (b != cur){
                        if (cur >= 0){
                            atomicAdd(&g_S2[cur*D1+c], rsum);
                            atomicMaxF(&g_Mx2[cur*D1+c], rmx);
                            atomicMinF(&g_Mn2[cur*D1+c], rmn);
                        }
                        rsum=0.f; rmx=NEGINF; rmn=POSINF; cur=b;
                    }
                    rsum += v; rmx = fmaxf(rmx,v); rmn = fminf(rmn,v);
                }
            }
        }
    }
    if (cur >= 0){
        atomicAdd(&g_S2[cur*D1+c], rsum);
        atomicMaxF(&g_Mx2[cur*D1+c], rmx);
        atomicMinF(&g_Mn2[cur*D1+c], rmn);
    }
    atomicAdd(&g_sum2[c], lsum);
    atomicAdd(&g_sq2[c],  lsq);
}

__global__ void k_stats2(const float* __restrict__ g2, const float* __restrict__ be2){
    int c = threadIdx.x;
    float m = g_sum2[c]*(1.0f/NN);
    float v = g_sq2[c]*(1.0f/NN) - m*m;
    float s = g2[c]*rsqrtf(v+EPSV);
    g_s2[c] = s; g_t2[c] = be2[c] - m*s;
}

// assemble pooled[1248] per batch: apply BN affine to raw aggregates
__global__ __launch_bounds__(416) void k_assemble(){
    int b = blockIdx.x, c = threadIdx.x;
    float cnt = g_cnt[b];
    float cntc = fmaxf(cnt, 1.f);
    float S, Mx, Mn, s, t;
    if (c < D1){
        S = g_S2[b*D1+c]; Mx = g_Mx2[b*D1+c]; Mn = g_Mn2[b*D1+c];
        s = g_s2[c]; t = g_t2[c];
    } else if (c < 400){
        int k = c - D1;
        S = g_S1[b*D0+k]; Mx = g_Mx1[b*D0+k]; Mn = g_Mn1[b*D0+k];
        s = g_s1[k]; t = g_t1[k];
    } else {
        int k = c - 400;
        S = g_Sx[b*16+k]; Mx = g_Mxx[b*16+k]; Mn = 0.f;
        s = 1.f; t = 0.f;
    }
    float sum = s*S + t*cnt;
    float mx  = (s >= 0.f) ? s*Mx + t : s*Mn + t;
    g_pooled[b*1248 + c]       = sum;
    g_pooled[b*1248 + 416 + c] = mx;
    g_pooled[b*1248 + 832 + c] = sum/cntc;
}

// hidden = PReLU(pooled @ W_l1 + b_l1); block = 8 batches x 48 cols
__global__ __launch_bounds__(384) void k_head1(const float* __restrict__ Wl1,
                                               const float* __restrict__ bl1,
                                               const float* __restrict__ alpha){
    __shared__ float sp[8*1252];
    int jc = blockIdx.x % 13, bg = blockIdx.x / 13;
    int t = threadIdx.x;
    for (int idx=t; idx<8*1248; idx+=384){
        int bb = idx/1248, k = idx%1248;
        sp[bb*1252+k] = g_pooled[(bg*8+bb)*1248 + k];
    }
    __syncthreads();
    int tj = t % 48, tb = t / 48;
    int j = jc*48 + tj;
    float acc = bl1[j];
    const float* pr = sp + tb*1252;
    #pragma unroll 4
    for (int k=0;k<1248;k++) acc = fmaf(pr[k], Wl1[k*624+j], acc);
    float a = alpha[0];
    g_hidden[(bg*8+tb)*624 + j] = (acc >= 0.f) ? acc : a*acc;
}

// logits + log_softmax: one warp per batch
__global__ void k_head2(const float* __restrict__ Wl2, const float* __restrict__ bl2,
                        float* __restrict__ out){
    int b = blockIdx.x, l = threadIdx.x;
    float p0=0.f, p1=0.f;
    for (int k=l; k<624; k+=32){
        float h = g_hidden[b*624+k];
        p0 = fmaf(h, Wl2[k*2],   p0);
        p1 = fmaf(h, Wl2[k*2+1], p1);
    }
    #pragma unroll
    for (int o=16;o;o>>=1){
        p0 += __shfl_down_sync(0xffffffffu, p0, o);
        p1 += __shfl_down_sync(0xffffffffu, p1, o);
    }
    if (l==0){
        float a0 = p0+bl2[0], a1 = p1+bl2[1];
        float m = fmaxf(a0,a1);
        float lse = m + logf(expf(a0-m)+expf(a1-m));
        out[b*2+0] = a0-lse;
        out[b*2+1] = a1-lse;
    }
}

extern "C" void kernel_launch(void* const* d_in, const int* in_sizes, int n_in,
                              void* d_out, int out_size) {
    const float* x    = (const float*)d_in[0];
    const int*   ei   = (const int*)  d_in[1];
    const float* ea   = (const float*)d_in[2];
    const int*   batch= (const int*)  d_in[3];
    const float* Wm1  = (const float*)d_in[4];
    const float* bm1  = (const float*)d_in[5];
    const float* We1  = (const float*)d_in[6];
    const float* be1b = (const float*)d_in[7];
    const float* Ws1  = (const float*)d_in[8];
    const float* bs1  = (const float*)d_in[9];
    const float* g1   = (const float*)d_in[10];
    const float* be1  = (const float*)d_in[11];
    const float* Wm2  = (const float*)d_in[12];
    const float* bm2  = (const float*)d_in[13];
    const float* We2  = (const float*)d_in[14];
    const float* be2b = (const float*)d_in[15];
    const float* g2   = (const float*)d_in[16];
    const float* be2  = (const float*)d_in[17];
    const float* Wl1  = (const float*)d_in[18];
    const float* bl1  = (const float*)d_in[19];
    const float* alpha= (const float*)d_in[20];
    const float* Wl2  = (const float*)d_in[21];
    const float* bl2  = (const float*)d_in[22];
    const int* src = ei;
    const int* dst = ei + EE;
    float* out = (float*)d_out;

    int gnode = (NN + 63)/64;   // 782
    k_zero<<<1024, 256>>>();
    k_edge1<<<(EE+255)/256, 256>>>(src, dst, ea, x);
    k_edge2<<<(EE+255)/256, 256>>>(src, dst);
    k_pre1<<<gnode, 192>>>(Wm1, bm1, We1, be1b, Ws1, bs1, x, batch);
    k_stats1<<<1, D0>>>(g1, be1);
    k_composeG<<<59, D1>>>(Wm1, We1, Ws1, bm1, be1b, bs1, Wm2, We2, bm2, be2b);
    k_h2<<<gnode, D1>>>(x, batch);
    k_stats2<<<1, D1>>>(g2, be2);
    k_assemble<<<BB, 416>>>();
    k_head1<<<104, 384>>>(Wl1, bl1, alpha);
    k_head2<<<BB, 32>>>(Wl2, bl2, out);
}

// round 4
// speedup vs baseline: 1.4546x; 1.0396x over previous
#include <cuda_runtime.h>
#include <math.h>

#define NN 50000
#define EE 800000
#define D0 192
#define D1 208
#define BB 64
#define RT 64
#define RS 68
#define EPSV 1e-5f
#define NEGINF __int_as_float(0xff800000)
#define POSINF __int_as_float(0x7f800000)

// ---------------- device scratch ----------------
__device__ __align__(16) float g_xa[NN*16];
__device__ __align__(16) float g_A[NN*4];
__device__ __align__(16) float g_deg[NN];
__device__ __align__(16) float g_xaa[NN*16];
__device__ __align__(16) float g_Aa[NN*4];
__device__ __align__(16) float g_dega[NN];
__device__ float g_sum1[D0], g_sq1[D0], g_s1[D0], g_t1[D0];
__device__ float g_sum2[D1], g_sq2[D1], g_s2[D1], g_t2[D1];
__device__ float g_G[59*D1];
__device__ float g_S1[BB*D0], g_Mx1[BB*D0], g_Mn1[BB*D0];
__device__ float g_S2[BB*D1], g_Mx2[BB*D1], g_Mn2[BB*D1];
__device__ float g_Sx[BB*16], g_Mxx[BB*16];
__device__ float g_cnt[BB];
__device__ float g_pooled[BB*1248];
__device__ float g_hidden[BB*624];

// ---------------- helpers ----------------
__device__ __forceinline__ void red4(float* addr, float4 v){
    asm volatile("red.global.add.v4.f32 [%0], {%1,%2,%3,%4};"
                 :: "l"(addr), "f"(v.x), "f"(v.y), "f"(v.z), "f"(v.w) : "memory");
}
__device__ __forceinline__ void atomicMaxF(float* a, float v){
    if (v >= 0.0f) atomicMax((int*)a, __float_as_int(v));
    else           atomicMin((unsigned int*)a, __float_as_uint(v));
}
__device__ __forceinline__ void atomicMinF(float* a, float v){
    if (v >= 0.0f) atomicMin((int*)a, __float_as_int(v));
    else           atomicMax((unsigned int*)a, __float_as_uint(v));
}

// ---------------- kernels ----------------
__global__ void k_zero(){
    int tid = blockIdx.x*blockDim.x + threadIdx.x;
    int st  = gridDim.x*blockDim.x;
    for (int i=tid;i<NN*16;i+=st){ g_xa[i]=0.f; g_xaa[i]=0.f; }
    for (int i=tid;i<NN*4; i+=st){ g_A[i]=0.f;  g_Aa[i]=0.f;  }
    for (int i=tid;i<NN;   i+=st){ g_deg[i]=0.f; g_dega[i]=0.f; }
    for (int i=tid;i<BB*D0;i+=st){ g_S1[i]=0.f; g_Mx1[i]=NEGINF; g_Mn1[i]=POSINF; }
    for (int i=tid;i<BB*D1;i+=st){ g_S2[i]=0.f; g_Mx2[i]=NEGINF; g_Mn2[i]=POSINF; }
    for (int i=tid;i<BB*16;i+=st){ g_Sx[i]=0.f; g_Mxx[i]=NEGINF; }
    if (tid < D0){ g_sum1[tid]=0.f; g_sq1[tid]=0.f; }
    if (tid < D1){ g_sum2[tid]=0.f; g_sq2[tid]=0.f; }
    if (tid < BB) g_cnt[tid]=0.f;
}

__global__ void k_edge1(const int* __restrict__ src, const int* __restrict__ dst,
                        const float* __restrict__ ea, const float* __restrict__ x){
    int e = blockIdx.x*blockDim.x + threadIdx.x;
    if (e >= EE) return;
    int s = src[e], d = dst[e];
    const float4* xr = (const float4*)(x + (size_t)s*16);
    float4 v0=xr[0], v1=xr[1], v2=xr[2], v3=xr[3];
    float* xd = g_xa + (size_t)d*16;
    red4(xd, v0); red4(xd+4, v1); red4(xd+8, v2); red4(xd+12, v3);
    float4 a = ((const float4*)ea)[e];
    red4(g_A + (size_t)d*4, a);
    atomicAdd(g_deg + d, 1.0f);
}

__global__ void k_edge2(const int* __restrict__ src, const int* __restrict__ dst){
    int e = blockIdx.x*blockDim.x + threadIdx.x;
    if (e >= EE) return;
    int s = src[e], d = dst[e];
    const float4* xr = (const float4*)(g_xa + (size_t)s*16);
    float4 v0=xr[0], v1=xr[1], v2=xr[2], v3=xr[3];
    float* xd = g_xaa + (size_t)d*16;
    red4(xd, v0); red4(xd+4, v1); red4(xd+8, v2); red4(xd+12, v3);
    float4 a = *((const float4*)(g_A + (size_t)s*4));
    red4(g_Aa + (size_t)d*4, a);
    atomicAdd(g_dega + d, g_deg[s]);
}

// h1_pre GEMM + BN1 stats + pooling (uniform-block fast path)
__global__ __launch_bounds__(192) void k_pre1(
        const float* __restrict__ Wm1, const float* __restrict__ bm1,
        const float* __restrict__ We1, const float* __restrict__ be1b,
        const float* __restrict__ Ws1, const float* __restrict__ bs1,
        const float* __restrict__ x, const int* __restrict__ batch){
    __shared__ float fsm[37*RS];
    __shared__ int sbat[RT];
    int c = threadIdx.x;
    float w[37];
    #pragma unroll
    for (int k=0;k<16;k++) w[k]    = Wm1[k*D0+c];
    #pragma unroll
    for (int k=0;k<4;k++)  w[16+k] = We1[k*D0+c];
    #pragma unroll
    for (int k=0;k<16;k++) w[20+k] = Ws1[k*D0+c];
    w[36] = bm1[c] + be1b[c];
    float initv = bs1[c];
    int brow = blockIdx.x*RT;
    int nrows = min(RT, NN - brow);
    for (int idx=c; idx<RT*16; idx+=192){
        int r=idx>>4, k=idx&15; bool ok=r<nrows; int row=brow+r;
        fsm[k*RS+r]      = ok ? g_xa[(size_t)row*16+k] : 0.f;
        fsm[(20+k)*RS+r] = ok ? x[(size_t)row*16+k]    : 0.f;
    }
    for (int idx=c; idx<RT*4; idx+=192){
        int r=idx>>2, k=idx&3; bool ok=r<nrows; int row=brow+r;
        fsm[(16+k)*RS+r] = ok ? g_A[(size_t)row*4+k] : 0.f;
    }
    for (int idx=c; idx<RT; idx+=192){
        bool ok=idx<nrows; int row=brow+idx;
        fsm[36*RS+idx] = ok ? g_deg[row] : 0.f;
        sbat[idx] = ok ? batch[row] : -1;
    }
    __syncthreads();
    bool uniform = (sbat[0] == sbat[nrows-1]);
    float lsum=0.f, lsq=0.f;
    float rsum=0.f, rmx=NEGINF, rmn=POSINF;
    int cur = sbat[0];
    for (int g8=0; g8<RT/8; ++g8){
        float4 a0 = make_float4(initv,initv,initv,initv);
        float4 a1 = a0;
        const float* fp = fsm + g8*8;
        #pragma unroll
        for (int k=0;k<37;k++){
            float4 f0 = *(const float4*)(fp + k*RS);
            float4 f1 = *(const float4*)(fp + k*RS + 4);
            a0.x = fmaf(w[k], f0.x, a0.x); a0.y = fmaf(w[k], f0.y, a0.y);
            a0.z = fmaf(w[k], f0.z, a0.z); a0.w = fmaf(w[k], f0.w, a0.w);
            a1.x = fmaf(w[k], f1.x, a1.x); a1.y = fmaf(w[k], f1.y, a1.y);
            a1.z = fmaf(w[k], f1.z, a1.z); a1.w = fmaf(w[k], f1.w, a1.w);
        }
        float vals[8] = {a0.x,a0.y,a0.z,a0.w,a1.x,a1.y,a1.z,a1.w};
        int rb = g8*8;
        if (uniform){
            #pragma unroll
            for (int q=0;q<8;q++){
                if (rb+q < nrows){
                    float v = vals[q];
                    lsum += v; lsq = fmaf(v,v,lsq);
                    rsum += v; rmx = fmaxf(rmx,v); rmn = fminf(rmn,v);
                }
            }
        } else {
            #pragma unroll
            for (int q=0;q<8;q++){
                int r = rb+q;
                if (r < nrows){
                    float v = vals[q];
                    lsum += v; lsq = fmaf(v,v,lsq);
                    int b = sbat[r];
                    if (b != cur){
                        atomicAdd(&g_S1[cur*D0+c], rsum);
                        atomicMaxF(&g_Mx1[cur*D0+c], rmx);
                        atomicMinF(&g_Mn1[cur*D0+c], rmn);
                        rsum=0.f; rmx=NEGINF; rmn=POSINF; cur=b;
                    }
                    rsum += v; rmx = fmaxf(rmx,v); rmn = fminf(rmn,v);
                }
            }
        }
    }
    atomicAdd(&g_S1[cur*D0+c], rsum);
    atomicMaxF(&g_Mx1[cur*D0+c], rmx);
    atomicMinF(&g_Mn1[cur*D0+c], rmn);
    atomicAdd(&g_sum1[c], lsum);
    atomicAdd(&g_sq1[c],  lsq);
    // x pooling + count: warp-0 epilogue over the smem tile
    if (c < 16){
        float xs=0.f, xmx=NEGINF, rc=0.f;
        int cur2 = sbat[0];
        for (int r=0;r<nrows;r++){
            int b = sbat[r];
            if (b != cur2){
                atomicAdd(&g_Sx[cur2*16+c], xs);
                atomicMaxF(&g_Mxx[cur2*16+c], xmx);
                if (c==0) atomicAdd(&g_cnt[cur2], rc);
                xs=0.f; xmx=NEGINF; rc=0.f; cur2=b;
            }
            float xv = fsm[(20+c)*RS+r];
            xs += xv; xmx = fmaxf(xmx,xv); rc += 1.f;
        }
        atomicAdd(&g_Sx[cur2*16+c], xs);
        atomicMaxF(&g_Mxx[cur2*16+c], xmx);
        if (c==0) atomicAdd(&g_cnt[cur2], rc);
    }
}

__global__ void k_stats1(const float* __restrict__ g1, const float* __restrict__ be1){
    int c = threadIdx.x;
    float m = g_sum1[c]*(1.0f/NN);
    float v = g_sq1[c]*(1.0f/NN) - m*m;
    float s = g1[c]*rsqrtf(v+EPSV);
    g_s1[c] = s; g_t1[c] = be1[c] - m*s;
}

// G[59,208]: h2_pre = F @ G,  F=[xaa(16),Aa(4),xa(16),A(4),x(16),dega,deg,1]
__global__ void k_composeG(
        const float* __restrict__ Wm1, const float* __restrict__ We1,
        const float* __restrict__ Ws1, const float* __restrict__ bm1,
        const float* __restrict__ be1b, const float* __restrict__ bs1,
        const float* __restrict__ Wm2, const float* __restrict__ We2,
        const float* __restrict__ bm2, const float* __restrict__ be2b){
    int c = threadIdx.x;
    int f = blockIdx.x;
    float acc = 0.f;
    if (f < 16){
        const float* wr = Wm1 + f*D0;
        for (int j=0;j<D0;j++) acc = fmaf(wr[j]*g_s1[j], Wm2[j*D1+c], acc);
    } else if (f < 20){
        const float* wr = We1 + (f-16)*D0;
        for (int j=0;j<D0;j++) acc = fmaf(wr[j]*g_s1[j], Wm2[j*D1+c], acc);
    } else if (f < 36){
        int k = f-20;
        const float* wr = Ws1 + k*D0;
        for (int j=0;j<D0;j++) acc = fmaf(wr[j]*g_s1[j], Wm2[j*D1+c], acc);
        acc += Wm2[(D0+k)*D1+c];
        if (c < D0) acc += Wm1[k*D0+c]*g_s1[c];
    } else if (f < 40){
        int k = f-36;
        acc = We2[k*D1+c] + ((c<D0) ? We1[k*D0+c]*g_s1[c] : 0.f);
    } else if (f < 56){
        int k = f-40;
        acc = (c<D0) ? Ws1[k*D0+c]*g_s1[c] : ((c-D0==k) ? 1.f : 0.f);
    } else if (f == 56){
        for (int j=0;j<D0;j++) acc = fmaf((bm1[j]+be1b[j])*g_s1[j], Wm2[j*D1+c], acc);
    } else if (f == 57){
        for (int j=0;j<D0;j++) acc = fmaf(bs1[j]*g_s1[j]+g_t1[j], Wm2[j*D1+c], acc);
        acc += bm2[c]+be2b[c];
        if (c < D0) acc += (bm1[c]+be1b[c])*g_s1[c];
    } else {
        acc = (c<D0) ? bs1[c]*g_s1[c]+g_t1[c] : 0.f;
    }
    g_G[f*D1+c] = acc;
}

// h2_pre = F @ G + BN2 stats + pooling (uniform-block fast path)
__global__ __launch_bounds__(208) void k_h2(const float* __restrict__ x,
                                            const int* __restrict__ batch){
    __shared__ float fsm[59*RS];
    __shared__ int sbat[RT];
    int c = threadIdx.x;
    float w[59];
    #pragma unroll
    for (int f=0; f<59; f++) w[f] = g_G[f*D1+c];
    int brow = blockIdx.x*RT;
    int nrows = min(RT, NN - brow);
    for (int idx=c; idx<RT*16; idx+=208){
        int r=idx>>4, k=idx&15; bool ok=r<nrows; int row=brow+r;
        fsm[k*RS+r]      = ok ? g_xaa[(size_t)row*16+k] : 0.f;
        fsm[(20+k)*RS+r] = ok ? g_xa [(size_t)row*16+k] : 0.f;
        fsm[(40+k)*RS+r] = ok ? x    [(size_t)row*16+k] : 0.f;
    }
    for (int idx=c; idx<RT*4; idx+=208){
        int r=idx>>2, k=idx&3; bool ok=r<nrows; int row=brow+r;
        fsm[(16+k)*RS+r] = ok ? g_Aa[(size_t)row*4+k] : 0.f;
        fsm[(36+k)*RS+r] = ok ? g_A [(size_t)row*4+k] : 0.f;
    }
    for (int idx=c; idx<RT; idx+=208){
        bool ok=idx<nrows; int row=brow+idx;
        fsm[56*RS+idx] = ok ? g_dega[row] : 0.f;
        fsm[57*RS+idx] = ok ? g_deg[row]  : 0.f;
        fsm[58*RS+idx] = ok ? 1.f : 0.f;
        sbat[idx] = ok ? batch[row] : -1;
    }
    __syncthreads();
    bool uniform = (sbat[0] == sbat[nrows-1]);
    float lsum=0.f, lsq=0.f;
    float rsum=0.f, rmx=NEGINF, rmn=POSINF;
    int cur = sbat[0];
    for (int g8=0; g8<RT/8; ++g8){
        float4 a0 = make_float4(0.f,0.f,0.f,0.f);
        float4 a1 = a0;
        const float* fp = fsm + g8*8;
        #pragma unroll
        for (int k=0;k<59;k++){
            float4 f0 = *(const float4*)(fp + k*RS);
            float4 f1 = *(const float4*)(fp + k*RS + 4);
            a0.x = fmaf(w[k], f0.x, a0.x); a0.y = fmaf(w[k], f0.y, a0.y);
            a0.z = fmaf(w[k], f0.z, a0.z); a0.w = fmaf(w[k], f0.w, a0.w);
            a1.x = fmaf(w[k], f1.x, a1.x); a1.y = fmaf(w[k], f1.y, a1.y);
            a1.z = fmaf(w[k], f1.z, a1.z); a1.w = fmaf(w[k], f1.w, a1.w);
        }
        float vals[8] = {a0.x,a0.y,a0.z,a0.w,a1.x,a1.y,a1.z,a1.w};
        int rb = g8*8;
        if (uniform){
            #pragma unroll
            for (int q=0;q<8;q++){
                if (rb+q < nrows){
                    float v = vals[q];
                    lsum += v; lsq = fmaf(v,v,lsq);
                    rsum += v; rmx = fmaxf(rmx,v); rmn = fminf(rmn,v);
                }
            }
        } else {
            #pragma unroll
            for (int q=0;q<8;q++){
                int r = rb+q;
                if (r < nrows){
                    float v = vals[q];
                    lsum += v; lsq = fmaf(v,v,lsq);
                    int b = sbat[r];
                    if (b != cur){
                        atomicAdd(&g_S2[cur*D1+c], rsum);
                        atomicMaxF(&g_Mx2[cur*D1+c], rmx);
                        atomicMinF(&g_Mn2[cur*D1+c], rmn);
                        rsum=0.f; rmx=NEGINF; rmn=POSINF; cur=b;
                    }
                    rsum += v; rmx = fmaxf(rmx,v); rmn = fminf(rmn,v);
                }
            }
        }
    }
    atomicAdd(&g_S2[cur*D1+c], rsum);
    atomicMaxF(&g_Mx2[cur*D1+c], rmx);
    atomicMinF(&g_Mn2[cur*D1+c], rmn);
    atomicAdd(&g_sum2[c], lsum);
    atomicAdd(&g_sq2[c],  lsq);
}

__global__ void k_stats2(const float* __restrict__ g2, const float* __restrict__ be2){
    int c = threadIdx.x;
    float m = g_sum2[c]*(1.0f/NN);
    float v = g_sq2[c]*(1.0f/NN) - m*m;
    float s = g2[c]*rsqrtf(v+EPSV);
    g_s2[c] = s; g_t2[c] = be2[c] - m*s;
}

// assemble pooled[1248] per batch: apply BN affine to raw aggregates
__global__ __launch_bounds__(416) void k_assemble(){
    int b = blockIdx.x, c = threadIdx.x;
    float cnt = g_cnt[b];
    float cntc = fmaxf(cnt, 1.f);
    float S, Mx, Mn, s, t;
    if (c < D1){
        S = g_S2[b*D1+c]; Mx = g_Mx2[b*D1+c]; Mn = g_Mn2[b*D1+c];
        s = g_s2[c]; t = g_t2[c];
    } else if (c < 400){
        int k = c - D1;
        S = g_S1[b*D0+k]; Mx = g_Mx1[b*D0+k]; Mn = g_Mn1[b*D0+k];
        s = g_s1[k]; t = g_t1[k];
    } else {
        int k = c - 400;
        S = g_Sx[b*16+k]; Mx = g_Mxx[b*16+k]; Mn = 0.f;
        s = 1.f; t = 0.f;
    }
    float sum = s*S + t*cnt;
    float mx  = (s >= 0.f) ? s*Mx + t : s*Mn + t;
    g_pooled[b*1248 + c]       = sum;
    g_pooled[b*1248 + 416 + c] = mx;
    g_pooled[b*1248 + 832 + c] = sum/cntc;
}

// hidden = PReLU(pooled @ W_l1 + b_l1); block = 8 batches x 48 cols
__global__ __launch_bounds__(384) void k_head1(const float* __restrict__ Wl1,
                                               const float* __restrict__ bl1,
                                               const float* __restrict__ alpha){
    __shared__ float sp[8*1252];
    int jc = blockIdx.x % 13, bg = blockIdx.x / 13;
    int t = threadIdx.x;
    for (int idx=t; idx<8*1248; idx+=384){
        int bb = idx/1248, k = idx%1248;
        sp[bb*1252+k] = g_pooled[(bg*8+bb)*1248 + k];
    }
    __syncthreads();
    int tj = t % 48, tb = t / 48;
    int j = jc*48 + tj;
    float acc = bl1[j];
    const float* pr = sp + tb*1252;
    #pragma unroll 4
    for (int k=0;k<1248;k++) acc = fmaf(pr[k], Wl1[k*624+j], acc);
    float a = alpha[0];
    g_hidden[(bg*8+tb)*624 + j] = (acc >= 0.f) ? acc : a*acc;
}

// logits + log_softmax: one warp per batch
__global__ void k_head2(const float* __restrict__ Wl2, const float* __restrict__ bl2,
                        float* __restrict__ out){
    int b = blockIdx.x, l = threadIdx.x;
    float p0=0.f, p1=0.f;
    for (int k=l; k<624; k+=32){
        float h = g_hidden[b*624+k];
        p0 = fmaf(h, Wl2[k*2],   p0);
        p1 = fmaf(h, Wl2[k*2+1], p1);
    }
    #pragma unroll
    for (int o=16;o;o>>=1){
        p0 += __shfl_down_sync(0xffffffffu, p0, o);
        p1 += __shfl_down_sync(0xffffffffu, p1, o);
    }
    if (l==0){
        float a0 = p0+bl2[0], a1 = p1+bl2[1];
        float m = fmaxf(a0,a1);
        float lse = m + logf(expf(a0-m)+expf(a1-m));
        out[b*2+0] = a0-lse;
        out[b*2+1] = a1-lse;
    }
}

extern "C" void kernel_launch(void* const* d_in, const int* in_sizes, int n_in,
                              void* d_out, int out_size) {
    const float* x    = (const float*)d_in[0];
    const int*   ei   = (const int*)  d_in[1];
    const float* ea   = (const float*)d_in[2];
    const int*   batch= (const int*)  d_in[3];
    const float* Wm1  = (const float*)d_in[4];
    const float* bm1  = (const float*)d_in[5];
    const float* We1  = (const float*)d_in[6];
    const float* be1b = (const float*)d_in[7];
    const float* Ws1  = (const float*)d_in[8];
    const float* bs1  = (const float*)d_in[9];
    const float* g1   = (const float*)d_in[10];
    const float* be1  = (const float*)d_in[11];
    const float* Wm2  = (const float*)d_in[12];
    const float* bm2  = (const float*)d_in[13];
    const float* We2  = (const float*)d_in[14];
    const float* be2b = (const float*)d_in[15];
    const float* g2   = (const float*)d_in[16];
    const float* be2  = (const float*)d_in[17];
    const float* Wl1  = (const float*)d_in[18];
    const float* bl1  = (const float*)d_in[19];
    const float* alpha= (const float*)d_in[20];
    const float* Wl2  = (const float*)d_in[21];
    const float* bl2  = (const float*)d_in[22];
    const int* src = ei;
    const int* dst = ei + EE;
    float* out = (float*)d_out;

    int gnode = (NN + RT - 1)/RT;   // 782
    k_zero<<<1024, 256>>>();
    k_edge1<<<(EE+255)/256, 256>>>(src, dst, ea, x);
    k_edge2<<<(EE+255)/256, 256>>>(src, dst);
    k_pre1<<<gnode, 192>>>(Wm1, bm1, We1, be1b, Ws1, bs1, x, batch);
    k_stats1<<<1, D0>>>(g1, be1);
    k_composeG<<<59, D1>>>(Wm1, We1, Ws1, bm1, be1b, bs1, Wm2, We2, bm2, be2b);
    k_h2<<<gnode, D1>>>(x, batch);
    k_stats2<<<1, D1>>>(g2, be2);
    k_assemble<<<BB, 416>>>();
    k_head1<<<104, 384>>>(Wl1, bl1, alpha);
    k_head2<<<BB, 32>>>(Wl2, bl2, out);
}